// round 10
// baseline (speedup 1.0000x reference)
#include <cuda_runtime.h>
#include <cstdint>

// STFT via 2048-pt complex FFT (two real frames per FFT: A=re, B=im).
// DIF radix 8-8-8-4, XOR-swizzled single 16KB smem buffer, fused
// conjugate-split epilogue, packed f32x2 add/sub.
// R10: max-shared carveout so the 8th 16KB CTA fits per SM (R9 showed the
// smem carveout, not regs, capped occupancy at 7); pass-2 twiddle from
// constants (n3 has only 4 values) instead of __sincosf.

#define WINDOW   2048
#define STRIDE   512
#define FREQ     1024
#define FRAMES   63
#define SIG_LEN  32256
#define BATCH    64
#define PAD_L    768
#define NT       256
#define NPAIRS   ((BATCH * FRAMES) / 2)   // 2016

// Packed complex add/sub: one f32x2 op instead of two FADD.
__device__ __forceinline__ float2 cadd(float2 a, float2 b) {
    float2 r;
    asm("{\n\t.reg .b64 ra, rb, rc;\n\t"
        "mov.b64 ra, {%2, %3};\n\t"
        "mov.b64 rb, {%4, %5};\n\t"
        "add.rn.f32x2 rc, ra, rb;\n\t"
        "mov.b64 {%0, %1}, rc;\n\t}"
        : "=f"(r.x), "=f"(r.y)
        : "f"(a.x), "f"(a.y), "f"(b.x), "f"(b.y));
    return r;
}
__device__ __forceinline__ float2 csub(float2 a, float2 b) {
    float2 r;
    asm("{\n\t.reg .b64 ra, rb, rc;\n\t"
        "mov.b64 ra, {%2, %3};\n\t"
        "mov.b64 rb, {%4, %5};\n\t"
        "sub.rn.f32x2 rc, ra, rb;\n\t"
        "mov.b64 {%0, %1}, rc;\n\t}"
        : "=f"(r.x), "=f"(r.y)
        : "f"(a.x), "f"(a.y), "f"(b.x), "f"(b.y));
    return r;
}
__device__ __forceinline__ float2 cmul(float2 a, float2 b) {
    return make_float2(fmaf(a.x, b.x, -a.y * b.y), fmaf(a.x, b.y, a.y * b.x));
}
__device__ __forceinline__ float2 cnegi(float2 a) { return make_float2(a.y, -a.x); }  // a * (-i)

// Logical swizzle: sw(k) = k ^ ((((k>>5)^(k>>8))&7)<<2), applied per pass
// algebraically with XOR.

// In-place 8-point DFT: E[q] = sum_j E_in[j] * exp(-2*pi*i*j*q/8)
__device__ __forceinline__ void dft8(float2* E) {
    const float R = 0.70710678118654752440f;
    float2 s0 = cadd(E[0], E[4]), s1 = cadd(E[1], E[5]);
    float2 s2 = cadd(E[2], E[6]), s3 = cadd(E[3], E[7]);
    float2 d0 = csub(E[0], E[4]), d1 = csub(E[1], E[5]);
    float2 d2 = csub(E[2], E[6]), d3 = csub(E[3], E[7]);
    d1 = make_float2(R * (d1.x + d1.y), R * (d1.y - d1.x));
    d2 = cnegi(d2);
    d3 = make_float2(R * (d3.y - d3.x), -R * (d3.x + d3.y));
    float2 A0 = cadd(s0, s2), A1 = cadd(s1, s3);
    float2 B0 = csub(s0, s2), B1 = cnegi(csub(s1, s3));
    E[0] = cadd(A0, A1); E[2] = cadd(B0, B1);
    E[4] = csub(A0, A1); E[6] = csub(B0, B1);
    float2 C0 = cadd(d0, d2), C1 = cadd(d1, d3);
    float2 D0 = csub(d0, d2), D1 = cnegi(csub(d1, d3));
    E[1] = cadd(C0, C1); E[3] = cadd(D0, D1);
    E[5] = csub(C0, C1); E[7] = csub(D0, D1);
}

__device__ __forceinline__ void dft4(float2* F) {
    float2 A0 = cadd(F[0], F[2]), A1 = cadd(F[1], F[3]);
    float2 B0 = csub(F[0], F[2]), B1 = cnegi(csub(F[1], F[3]));
    F[0] = cadd(A0, A1); F[1] = cadd(B0, B1);
    F[2] = csub(A0, A1); F[3] = csub(B0, B1);
}

// Store E[q]*w1^q at zz[idx[q]] (idx pre-swizzled). Serial twiddle chain.
__device__ __forceinline__ void twiddle_store(float2* zz, const float2* E,
                                              const int* idx, float2 w1) {
    zz[idx[0]] = E[0];
    zz[idx[1]] = cmul(E[1], w1);
    float2 w = w1;
    #pragma unroll
    for (int q = 2; q < 8; q++) {
        w = cmul(w, w1);
        zz[idx[q]] = cmul(E[q], w);
    }
}

__global__ __launch_bounds__(NT, 8) void stft_kernel(const float* __restrict__ x,
                                                     float* __restrict__ out)
{
    __shared__ __align__(16) float2 zz[2048];

    const int t = threadIdx.x;
    const int pr = blockIdx.x;
    const int m0 = 2 * pr, m1 = m0 + 1;
    const int ba = m0 / FRAMES, fa = m0 - ba * FRAMES;
    const int bb = m1 / FRAMES, fb = m1 - bb * FRAMES;
    const float* xA = x + ba * SIG_LEN;
    const float* xB = x + bb * SIG_LEN;
    const int baseA = fa * STRIDE - PAD_L;
    const int baseB = fb * STRIDE - PAD_L;

    float2 E[8];
    int idx[8];

    // ---- pass 0 (DIF, N=2048, M=256): coalesced gmem loads x[t+256j],
    // half-Hann (0.5x folded from epilogue) on the fly, DFT8 over j,
    // twiddle W_2048^(t*q), store block q. sw slot: (t>>5) ^ q.
    {
        float sn0, cs0;
        __sincosf(3.06796157577128245e-3f * (float)t, &sn0, &cs0);  // 2*pi*t/2048

        float va[8], vb[8];
        const bool interior = (baseA >= 0) && (baseA <= SIG_LEN - WINDOW) &&
                              (baseB >= 0) && (baseB <= SIG_LEN - WINDOW);
        if (interior) {
            #pragma unroll
            for (int j = 0; j < 8; j++) {
                va[j] = xA[baseA + t + 256 * j];
                vb[j] = xB[baseB + t + 256 * j];
            }
        } else {
            #pragma unroll
            for (int j = 0; j < 8; j++) {
                int ia = baseA + t + 256 * j;
                int ib = baseB + t + 256 * j;
                va[j] = ((unsigned)ia < (unsigned)SIG_LEN) ? xA[ia] : 0.0f;
                vb[j] = ((unsigned)ib < (unsigned)SIG_LEN) ? xB[ib] : 0.0f;
            }
        }

        const float R = 0.70710678118654752440f;
        float cs = cs0, sn = sn0;
        #pragma unroll
        for (int j = 0; j < 4; j++) {
            float w0 = 0.25f - 0.25f * cs;   // 0.5 * hann(t + 256j)
            float w1 = 0.5f - w0;            // 0.5 * hann(t + 256j + 1024)
            E[j]     = make_float2(w0 * va[j],     w0 * vb[j]);
            E[j + 4] = make_float2(w1 * va[j + 4], w1 * vb[j + 4]);
            float c2 = (cs - sn) * R;        // window phase += pi/4
            float s2 = (sn + cs) * R;
            cs = c2; sn = s2;
        }
        dft8(E);
        int s5 = t >> 5;
        #pragma unroll
        for (int q = 0; q < 8; q++) idx[q] = (t + 256 * q) ^ ((s5 ^ q) << 2);
        twiddle_store(zz, E, idx, make_float2(cs0, -sn0));  // W_2048^t
    }
    __syncthreads();

    // ---- pass 1 (N=256, M=32): warp q owns 256-block q; in-place, intra-warp.
    // sw slot for k=q*256+n2+32j: q ^ j.
    {
        int n2 = t & 31, q = t >> 5;
        int base = q * 256 + n2;
        #pragma unroll
        for (int j = 0; j < 8; j++) idx[j] = (base + 32 * j) ^ ((q ^ j) << 2);
        #pragma unroll
        for (int j = 0; j < 8; j++) E[j] = zz[idx[j]];
        dft8(E);
        float2 w1; __sincosf(-2.45436926061702597e-2f * (float)n2, &w1.y, &w1.x); // W_256^n2
        twiddle_store(zz, E, idx, w1);
    }
    __syncwarp();

    // ---- pass 2 (N=32, M=4): 4 threads per 32-block, intra-warp.
    // sw slot for k=b*32+n3+4j: (b ^ (b>>3)) & 7 — constant over j; XOR hits
    // only the j field, so idx = b*32 + n3 + 4*(j ^ slot).
    // Twiddle W_32^n3 has only 4 values -> constant select, no MUFU.
    {
        int n3 = t & 3, b = t >> 2;
        int slot = (b ^ (b >> 3)) & 7;
        int base = b * 32 + n3;
        #pragma unroll
        for (int j = 0; j < 8; j++) idx[j] = base + 4 * (j ^ slot);
        #pragma unroll
        for (int j = 0; j < 8; j++) E[j] = zz[idx[j]];
        dft8(E);
        float2 w1;
        w1.x = (n3 & 2) ? ((n3 & 1) ? 0.83146961230254524f : 0.92387953251128676f)
                        : ((n3 & 1) ? 0.98078528040323044f : 1.0f);
        w1.y = (n3 & 2) ? ((n3 & 1) ? -0.55557023301960222f : -0.38268343236508978f)
                        : ((n3 & 1) ? -0.19509032201612827f : 0.0f);
        twiddle_store(zz, E, idx, w1);
    }
    __syncthreads();

    // ---- pass 3 (N=4) + fused conjugate-split epilogue.
    // f = 512*q3 + c, c = 64*q2+8*q1+q0, group g = digitrev8(c), element 4g+q3.
    // sw slot: ((g>>3)^(g>>6))&7 — constant per group -> base 4*(g^slot).
    // Values arrive pre-scaled by 0.5:
    //   S = Zf + Zg = (outRA, outRB),  D = Zg - Zf = (outIB, -outIA).
    {
        int ca = t;
        int cb = t ? (512 - t) : 256;
        int ga = ((ca & 7) << 6) | (ca & 56) | (ca >> 6);
        int gb = ((cb & 7) << 6) | (cb & 56) | (cb >> 6);
        float2 G[4], H[4];
        {
            int ia = 4 * (ga ^ (((ga >> 3) ^ (ga >> 6)) & 7));
            float4 v0 = *(const float4*)&zz[ia];
            float4 v1 = *(const float4*)&zz[ia + 2];
            G[0] = make_float2(v0.x, v0.y); G[1] = make_float2(v0.z, v0.w);
            G[2] = make_float2(v1.x, v1.y); G[3] = make_float2(v1.z, v1.w);
            int ib = 4 * (gb ^ (((gb >> 3) ^ (gb >> 6)) & 7));
            float4 u0 = *(const float4*)&zz[ib];
            float4 u1 = *(const float4*)&zz[ib + 2];
            H[0] = make_float2(u0.x, u0.y); H[1] = make_float2(u0.z, u0.w);
            H[2] = make_float2(u1.x, u1.y); H[3] = make_float2(u1.z, u1.w);
        }
        dft4(G);   // G[q3] = 0.5 * Z[512*q3 + ca]
        dft4(H);   // H[q3] = 0.5 * Z[512*q3 + cb]

        int    bins[4];
        float2 zf[4], zg[4];
        zf[0] = G[0]; zf[1] = G[1]; zf[2] = H[0]; zf[3] = H[1];
        if (t) {
            bins[0] = t;        zg[0] = H[3];   // Z[2048-t]
            bins[1] = t + 512;  zg[1] = H[2];   // Z[1536-t]
            bins[2] = 512 - t;  zg[2] = G[3];   // Z[1536+t]
            bins[3] = 1024 - t; zg[3] = G[2];   // Z[1024+t]
        } else {
            bins[0] = 0;   zg[0] = G[0];
            bins[1] = 512; zg[1] = G[3];
            bins[2] = 256; zg[2] = H[3];
            bins[3] = 768; zg[3] = H[2];
        }

        float* outR = out;
        float* outI = out + (size_t)(BATCH * FRAMES) * FREQ;
        size_t oA = (size_t)m0 * FREQ;
        size_t oB = (size_t)m1 * FREQ;
        #pragma unroll
        for (int i = 0; i < 4; i++) {
            int f = bins[i];
            float2 S = cadd(zf[i], zg[i]);   // (outRA, outRB)
            float2 D = csub(zg[i], zf[i]);   // (outIB, -outIA)
            outR[oA + f] = S.x;
            outR[oB + f] = S.y;
            outI[oA + f] = -D.y;
            outI[oB + f] = D.x;
        }
    }
}

extern "C" void kernel_launch(void* const* d_in, const int* in_sizes, int n_in,
                              void* d_out, int out_size)
{
    const float* x = (const float*)d_in[0];   // input_signal [64, 32256, 1]
    float* out = (float*)d_out;               // [2, 4032, 1024]

    // Request max shared-memory carveout so 8 CTAs x 16KB fit per SM.
    // Not a stream op / no allocation: capture-safe, idempotent, deterministic.
    static bool attr_set = false;
    if (!attr_set) {
        cudaFuncSetAttribute(stft_kernel,
                             cudaFuncAttributePreferredSharedMemoryCarveout,
                             cudaSharedmemCarveoutMaxShared);
        attr_set = true;
    }

    stft_kernel<<<NPAIRS, NT>>>(x, out);
}

// round 11
// speedup vs baseline: 1.0266x; 1.0266x over previous
#include <cuda_runtime.h>
#include <cstdint>

// STFT via 2048-pt complex FFT (two real frames per FFT: A=re, B=im).
// DIF radix 8-8-8-4, XOR-swizzled smem, fused conjugate-split epilogue,
// packed f32x2 add/sub.
// R11: TWO FFTs (4 frames) per CTA. idx[], sincos, window recurrence and
// the serial twiddle chains are shared between both FFT register streams
// (E[] and F[]); the two dft8 chains are independent -> 2x ILP. Second
// buffer addressing folds into LDS/STS immediate offsets.

#define WINDOW   2048
#define STRIDE   512
#define FREQ     1024
#define FRAMES   63
#define SIG_LEN  32256
#define BATCH    64
#define PAD_L    768
#define NT       256
#define NCTA     ((BATCH * FRAMES) / 4)   // 1008, 4 frames per CTA

// Packed complex add/sub: one f32x2 op instead of two FADD.
__device__ __forceinline__ float2 cadd(float2 a, float2 b) {
    float2 r;
    asm("{\n\t.reg .b64 ra, rb, rc;\n\t"
        "mov.b64 ra, {%2, %3};\n\t"
        "mov.b64 rb, {%4, %5};\n\t"
        "add.rn.f32x2 rc, ra, rb;\n\t"
        "mov.b64 {%0, %1}, rc;\n\t}"
        : "=f"(r.x), "=f"(r.y)
        : "f"(a.x), "f"(a.y), "f"(b.x), "f"(b.y));
    return r;
}
__device__ __forceinline__ float2 csub(float2 a, float2 b) {
    float2 r;
    asm("{\n\t.reg .b64 ra, rb, rc;\n\t"
        "mov.b64 ra, {%2, %3};\n\t"
        "mov.b64 rb, {%4, %5};\n\t"
        "sub.rn.f32x2 rc, ra, rb;\n\t"
        "mov.b64 {%0, %1}, rc;\n\t}"
        : "=f"(r.x), "=f"(r.y)
        : "f"(a.x), "f"(a.y), "f"(b.x), "f"(b.y));
    return r;
}
__device__ __forceinline__ float2 cmul(float2 a, float2 b) {
    return make_float2(fmaf(a.x, b.x, -a.y * b.y), fmaf(a.x, b.y, a.y * b.x));
}
__device__ __forceinline__ float2 cnegi(float2 a) { return make_float2(a.y, -a.x); }  // a * (-i)

// Logical swizzle: sw(k) = k ^ ((((k>>5)^(k>>8))&7)<<2), applied per pass
// algebraically with XOR (slots hoisted).

// In-place 8-point DFT: E[q] = sum_j E_in[j] * exp(-2*pi*i*j*q/8)
__device__ __forceinline__ void dft8(float2* E) {
    const float R = 0.70710678118654752440f;
    float2 s0 = cadd(E[0], E[4]), s1 = cadd(E[1], E[5]);
    float2 s2 = cadd(E[2], E[6]), s3 = cadd(E[3], E[7]);
    float2 d0 = csub(E[0], E[4]), d1 = csub(E[1], E[5]);
    float2 d2 = csub(E[2], E[6]), d3 = csub(E[3], E[7]);
    d1 = make_float2(R * (d1.x + d1.y), R * (d1.y - d1.x));
    d2 = cnegi(d2);
    d3 = make_float2(R * (d3.y - d3.x), -R * (d3.x + d3.y));
    float2 A0 = cadd(s0, s2), A1 = cadd(s1, s3);
    float2 B0 = csub(s0, s2), B1 = cnegi(csub(s1, s3));
    E[0] = cadd(A0, A1); E[2] = cadd(B0, B1);
    E[4] = csub(A0, A1); E[6] = csub(B0, B1);
    float2 C0 = cadd(d0, d2), C1 = cadd(d1, d3);
    float2 D0 = csub(d0, d2), D1 = cnegi(csub(d1, d3));
    E[1] = cadd(C0, C1); E[3] = cadd(D0, D1);
    E[5] = csub(C0, C1); E[7] = csub(D0, D1);
}

__device__ __forceinline__ void dft4(float2* F) {
    float2 A0 = cadd(F[0], F[2]), A1 = cadd(F[1], F[3]);
    float2 B0 = csub(F[0], F[2]), B1 = cnegi(csub(F[1], F[3]));
    F[0] = cadd(A0, A1); F[1] = cadd(B0, B1);
    F[2] = csub(A0, A1); F[3] = csub(B0, B1);
}

// Shared twiddle chain applied to two independent streams.
__device__ __forceinline__ void twiddle_store2(float2* z0, float2* z1,
                                               const float2* E, const float2* F,
                                               const int* idx, float2 w1) {
    z0[idx[0]] = E[0];
    z1[idx[0]] = F[0];
    z0[idx[1]] = cmul(E[1], w1);
    z1[idx[1]] = cmul(F[1], w1);
    float2 w = w1;
    #pragma unroll
    for (int q = 2; q < 8; q++) {
        w = cmul(w, w1);
        z0[idx[q]] = cmul(E[q], w);
        z1[idx[q]] = cmul(F[q], w);
    }
}

// Load + half-Hann window two frames (A->re, B->im) into E[8].
__device__ __forceinline__ void load_window(const float* __restrict__ xA, int baseA,
                                            const float* __restrict__ xB, int baseB,
                                            int t, float cs0, float sn0, float2* E) {
    float va[8], vb[8];
    const bool interior = (baseA >= 0) && (baseA <= SIG_LEN - WINDOW) &&
                          (baseB >= 0) && (baseB <= SIG_LEN - WINDOW);
    if (interior) {
        #pragma unroll
        for (int j = 0; j < 8; j++) {
            va[j] = xA[baseA + t + 256 * j];
            vb[j] = xB[baseB + t + 256 * j];
        }
    } else {
        #pragma unroll
        for (int j = 0; j < 8; j++) {
            int ia = baseA + t + 256 * j;
            int ib = baseB + t + 256 * j;
            va[j] = ((unsigned)ia < (unsigned)SIG_LEN) ? xA[ia] : 0.0f;
            vb[j] = ((unsigned)ib < (unsigned)SIG_LEN) ? xB[ib] : 0.0f;
        }
    }
    const float R = 0.70710678118654752440f;
    float cs = cs0, sn = sn0;
    #pragma unroll
    for (int j = 0; j < 4; j++) {
        float w0 = 0.25f - 0.25f * cs;   // 0.5 * hann(t + 256j)
        float w1 = 0.5f - w0;            // 0.5 * hann(t + 256j + 1024)
        E[j]     = make_float2(w0 * va[j],     w0 * vb[j]);
        E[j + 4] = make_float2(w1 * va[j + 4], w1 * vb[j + 4]);
        float c2 = (cs - sn) * R;        // window phase += pi/4
        float s2 = (sn + cs) * R;
        cs = c2; sn = s2;
    }
}

__global__ __launch_bounds__(NT, 4) void stft_kernel(const float* __restrict__ x,
                                                     float* __restrict__ out)
{
    __shared__ __align__(16) float2 zz[2][2048];   // one buffer per FFT

    const int t = threadIdx.x;
    const int m0 = 4 * blockIdx.x;   // frames m0 .. m0+3

    float2 E[8], F[8];
    int idx[8];

    float sn0, cs0;
    __sincosf(3.06796157577128245e-3f * (float)t, &sn0, &cs0);  // 2*pi*t/2048

    // ---- pass 0 (DIF, N=2048, M=256) for both FFTs; shared idx + chain.
    {
        {   // FFT 0: frames m0 (re), m0+1 (im)
            int ba = m0 / FRAMES,       fa = m0 - ba * FRAMES;
            int bb = (m0 + 1) / FRAMES, fb = (m0 + 1) - bb * FRAMES;
            load_window(x + ba * SIG_LEN, fa * STRIDE - PAD_L,
                        x + bb * SIG_LEN, fb * STRIDE - PAD_L, t, cs0, sn0, E);
        }
        {   // FFT 1: frames m0+2 (re), m0+3 (im)
            int ba = (m0 + 2) / FRAMES, fa = (m0 + 2) - ba * FRAMES;
            int bb = (m0 + 3) / FRAMES, fb = (m0 + 3) - bb * FRAMES;
            load_window(x + ba * SIG_LEN, fa * STRIDE - PAD_L,
                        x + bb * SIG_LEN, fb * STRIDE - PAD_L, t, cs0, sn0, F);
        }
        dft8(E);
        dft8(F);
        int s5 = t >> 5;
        #pragma unroll
        for (int q = 0; q < 8; q++) idx[q] = (t + 256 * q) ^ ((s5 ^ q) << 2);
        twiddle_store2(zz[0], zz[1], E, F, idx, make_float2(cs0, -sn0)); // W_2048^t
    }
    __syncthreads();

    // ---- pass 1 (N=256, M=32): warp q owns 256-block q; intra-warp in-place.
    // sw slot for k=q*256+n2+32j: q ^ j.
    {
        int n2 = t & 31, q = t >> 5;
        int base = q * 256 + n2;
        #pragma unroll
        for (int j = 0; j < 8; j++) idx[j] = (base + 32 * j) ^ ((q ^ j) << 2);
        #pragma unroll
        for (int j = 0; j < 8; j++) { E[j] = zz[0][idx[j]]; F[j] = zz[1][idx[j]]; }
        dft8(E);
        dft8(F);
        float2 w1; __sincosf(-2.45436926061702597e-2f * (float)n2, &w1.y, &w1.x); // W_256^n2
        twiddle_store2(zz[0], zz[1], E, F, idx, w1);
    }
    __syncwarp();

    // ---- pass 2 (N=32, M=4): 4 threads per 32-block, intra-warp.
    // slot (b^(b>>3))&7 constant over j -> idx = b*32 + n3 + 4*(j^slot).
    // W_32^n3 from constants (n3 in 0..3).
    {
        int n3 = t & 3, b = t >> 2;
        int slot = (b ^ (b >> 3)) & 7;
        int base = b * 32 + n3;
        #pragma unroll
        for (int j = 0; j < 8; j++) idx[j] = base + 4 * (j ^ slot);
        #pragma unroll
        for (int j = 0; j < 8; j++) { E[j] = zz[0][idx[j]]; F[j] = zz[1][idx[j]]; }
        dft8(E);
        dft8(F);
        float2 w1;
        w1.x = (n3 & 2) ? ((n3 & 1) ? 0.83146961230254524f : 0.92387953251128676f)
                        : ((n3 & 1) ? 0.98078528040323044f : 1.0f);
        w1.y = (n3 & 2) ? ((n3 & 1) ? -0.55557023301960222f : -0.38268343236508978f)
                        : ((n3 & 1) ? -0.19509032201612827f : 0.0f);
        twiddle_store2(zz[0], zz[1], E, F, idx, w1);
    }
    __syncthreads();

    // ---- pass 3 (N=4) + fused conjugate-split epilogue, per FFT.
    // f = 512*q3 + c, group g = digitrev8(c), element 4g+q3; slot per group
    // constant -> base 4*(g^slot), 16B-aligned. Values pre-scaled by 0.5:
    //   S = Zf + Zg = (outRA, outRB),  D = Zg - Zf = (outIB, -outIA).
    {
        int ca = t;
        int cb = t ? (512 - t) : 256;
        int ga = ((ca & 7) << 6) | (ca & 56) | (ca >> 6);
        int gb = ((cb & 7) << 6) | (cb & 56) | (cb >> 6);
        int ia = 4 * (ga ^ (((ga >> 3) ^ (ga >> 6)) & 7));
        int ib = 4 * (gb ^ (((gb >> 3) ^ (gb >> 6)) & 7));

        float* outR = out;
        float* outI = out + (size_t)(BATCH * FRAMES) * FREQ;

        #pragma unroll
        for (int ff = 0; ff < 2; ff++) {
            float2 G[4], H[4];
            {
                float4 v0 = *(const float4*)&zz[ff][ia];
                float4 v1 = *(const float4*)&zz[ff][ia + 2];
                G[0] = make_float2(v0.x, v0.y); G[1] = make_float2(v0.z, v0.w);
                G[2] = make_float2(v1.x, v1.y); G[3] = make_float2(v1.z, v1.w);
                float4 u0 = *(const float4*)&zz[ff][ib];
                float4 u1 = *(const float4*)&zz[ff][ib + 2];
                H[0] = make_float2(u0.x, u0.y); H[1] = make_float2(u0.z, u0.w);
                H[2] = make_float2(u1.x, u1.y); H[3] = make_float2(u1.z, u1.w);
            }
            dft4(G);   // G[q3] = 0.5 * Z[512*q3 + ca]
            dft4(H);   // H[q3] = 0.5 * Z[512*q3 + cb]

            int    bins[4];
            float2 zf[4], zg[4];
            zf[0] = G[0]; zf[1] = G[1]; zf[2] = H[0]; zf[3] = H[1];
            if (t) {
                bins[0] = t;        zg[0] = H[3];   // Z[2048-t]
                bins[1] = t + 512;  zg[1] = H[2];   // Z[1536-t]
                bins[2] = 512 - t;  zg[2] = G[3];   // Z[1536+t]
                bins[3] = 1024 - t; zg[3] = G[2];   // Z[1024+t]
            } else {
                bins[0] = 0;   zg[0] = G[0];
                bins[1] = 512; zg[1] = G[3];
                bins[2] = 256; zg[2] = H[3];
                bins[3] = 768; zg[3] = H[2];
            }

            size_t oA = (size_t)(m0 + 2 * ff) * FREQ;
            size_t oB = (size_t)(m0 + 2 * ff + 1) * FREQ;
            #pragma unroll
            for (int i = 0; i < 4; i++) {
                int f = bins[i];
                float2 S = cadd(zf[i], zg[i]);   // (outRA, outRB)
                float2 D = csub(zg[i], zf[i]);   // (outIB, -outIA)
                outR[oA + f] = S.x;
                outR[oB + f] = S.y;
                outI[oA + f] = -D.y;
                outI[oB + f] = D.x;
            }
        }
    }
}

extern "C" void kernel_launch(void* const* d_in, const int* in_sizes, int n_in,
                              void* d_out, int out_size)
{
    const float* x = (const float*)d_in[0];   // input_signal [64, 32256, 1]
    float* out = (float*)d_out;               // [2, 4032, 1024]

    // 4 CTAs x 32KB smem per SM needs the max-shared carveout.
    // Capture-safe: not a stream op, no allocation, idempotent.
    static bool attr_set = false;
    if (!attr_set) {
        cudaFuncSetAttribute(stft_kernel,
                             cudaFuncAttributePreferredSharedMemoryCarveout,
                             cudaSharedmemCarveoutMaxShared);
        attr_set = true;
    }

    stft_kernel<<<NCTA, NT>>>(x, out);
}